// round 2
// baseline (speedup 1.0000x reference)
#include <cuda_runtime.h>
#include <cuda_bf16.h>
#include <stdint.h>

// Scratch (allocation-free rule: __device__ globals)
#define MAX_NODES 65536
__device__ int g_counts[MAX_NODES];
__device__ int g_is64;   // 1 if node_ids buffer is int64, 0 if int32

// ---------------------------------------------------------------------------
// Detect whether the ids buffer is int64 (little-endian high words all zero)
// or int32. Checks the first 64 odd 32-bit words; for random int32 ids in
// [0, 50000) the chance they are all zero is ~(1/50000)^64 ~ 0.
// ---------------------------------------------------------------------------
__global__ void detect_ids_dtype(const int* __restrict__ ids32)
{
    if (threadIdx.x == 0 && blockIdx.x == 0) {
        int all_zero = 1;
        #pragma unroll 8
        for (int i = 1; i < 128; i += 2) {
            if (ids32[i] != 0) { all_zero = 0; break; }
        }
        g_is64 = all_zero;
    }
}

// ---------------------------------------------------------------------------
// Init: zero the sums region (float4-wide), zero counts, and (optionally)
// write the unique_node_ids column (0..NN-1 as float).
// Launched with NN*32 threads; thread idx zeroes one float4 of sums.
// ---------------------------------------------------------------------------
__global__ void init_kernel(float4* __restrict__ sums4,
                            float*  __restrict__ ids_out,
                            int NN, int ids_mode)
{
    int idx = blockIdx.x * blockDim.x + threadIdx.x;
    int total = NN * 32;                    // NN*128 floats / 4
    if (idx < total) {
        sums4[idx] = make_float4(0.f, 0.f, 0.f, 0.f);
    }
    if (idx < NN) {
        g_counts[idx] = 0;
        if (ids_mode) ids_out[idx] = (float)idx;
    }
}

// ---------------------------------------------------------------------------
// Scatter: one warp per message row. Each lane loads one float4 (coalesced
// 512B per row) and issues a single red.global.add.v4.f32 into the L2-resident
// sums buffer. Lane 0 bumps the count.
// ---------------------------------------------------------------------------
__global__ void scatter_kernel(const void*  __restrict__ ids,
                               const float4* __restrict__ msgs4,
                               float* __restrict__ sums,
                               int n_msgs)
{
    int gtid = blockIdx.x * blockDim.x + threadIdx.x;
    int w    = gtid >> 5;
    int lane = gtid & 31;
    if (w >= n_msgs) return;

    int id;
    if (g_is64) id = (int)((const long long*)ids)[w];
    else        id = ((const int*)ids)[w];

    if (lane == 0) atomicAdd(&g_counts[id], 1);

    float4 v = msgs4[(size_t)w * 32 + lane];
    float* dst = sums + (size_t)id * 128 + lane * 4;
    asm volatile("red.global.add.v4.f32 [%0], {%1, %2, %3, %4};"
                 :: "l"(dst), "f"(v.x), "f"(v.y), "f"(v.z), "f"(v.w)
                 : "memory");
}

// ---------------------------------------------------------------------------
// Finalize: agg = sum / max(count, 1), float4-wide in place.
// ---------------------------------------------------------------------------
__global__ void finalize_kernel(float4* __restrict__ sums4, int NN)
{
    int idx = blockIdx.x * blockDim.x + threadIdx.x;
    int total = NN * 32;
    if (idx >= total) return;
    int node = idx >> 5;
    int c = g_counts[node];
    float inv = 1.0f / (float)(c > 0 ? c : 1);
    float4 v = sums4[idx];
    v.x *= inv; v.y *= inv; v.z *= inv; v.w *= inv;
    sums4[idx] = v;
}

// ---------------------------------------------------------------------------
// kernel_launch
// Inputs (metadata order): node_ids [1e6], messages [1e6,128] f32, num_nodes
// Output: tuple (unique_node_ids, agg) — assumed flattened/concatenated as
// float32. out_size % 129 == 0  -> [ids | agg];  else -> agg only.
// ---------------------------------------------------------------------------
extern "C" void kernel_launch(void* const* d_in, const int* in_sizes, int n_in,
                              void* d_out, int out_size)
{
    const void*   ids   = d_in[0];
    const float4* msgs4 = (const float4*)d_in[1];
    int n_msgs = in_sizes[1] / 128;

    int ids_mode, NN;
    if (out_size % 129 == 0) { ids_mode = 1; NN = out_size / 129; }
    else                     { ids_mode = 0; NN = out_size / 128; }

    float* out      = (float*)d_out;
    float* ids_out  = out;                      // first NN floats if ids_mode
    float* sums     = ids_mode ? (out + NN) : out;

    detect_ids_dtype<<<1, 32>>>((const int*)ids);

    {
        int total = NN * 32;
        int blk = 256;
        init_kernel<<<(total + blk - 1) / blk, blk>>>((float4*)sums, ids_out,
                                                      NN, ids_mode);
    }
    {
        int threads = n_msgs * 32;
        int blk = 256;
        scatter_kernel<<<(threads + blk - 1) / blk, blk>>>(ids, msgs4, sums,
                                                           n_msgs);
    }
    {
        int total = NN * 32;
        int blk = 256;
        finalize_kernel<<<(total + blk - 1) / blk, blk>>>((float4*)sums, NN);
    }
}